// round 13
// baseline (speedup 1.0000x reference)
#include <cuda_runtime.h>
#include <cuda_fp16.h>
#include <cstdint>

#define NN 50000
#define EE 800000
#define DDD 128
#define GGG 64
#define CCC 8
#define BUCKET 128   // max combined degree per node (Poisson(32): P(>=128) ~ 1e-35)

// ---------------- scratch ----------------
__device__ __half    g_h16[NN * DDD];        // fp16 feature table (layer input)
__device__ __half    g_a16[NN * 256];        // aggregated A [node][256] fp16
__device__ __half    g_w16[2 * 128 * 256];   // Wt fp16 [layer][n][k]
__device__ int       g_cnt[2 * NN];          // per-relation in-degree; INVARIANT: zero at entry & exit
__device__ float     g_isd[2 * NN];
__device__ int       g_cur[NN];              // bucket fill counts; INVARIANT: zero at entry & exit
__device__ unsigned  g_ebuf[NN * BUCKET];    // bucket entries: src | r<<16
__device__ int       g_bcnt[GGG];
__device__ float     g_pool[GGG * DDD];

// ================= helpers =================
__device__ __forceinline__ unsigned smem_u32(const void* p) {
    unsigned a;
    asm("{ .reg .u64 t; cvta.to.shared.u64 t, %1; cvt.u32.u64 %0, t; }" : "=r"(a) : "l"(p));
    return a;
}
__device__ __forceinline__ void cp16(unsigned dst, const void* gsrc, unsigned srcsize) {
    asm volatile("cp.async.cg.shared.global [%0], [%1], 16, %2;"
                 :: "r"(dst), "l"(__cvta_generic_to_global((void*)gsrc)), "r"(srcsize) : "memory");
}
__device__ __forceinline__ void cp_commit() { asm volatile("cp.async.commit_group;" ::: "memory"); }
template <int N> __device__ __forceinline__ void cp_wait() {
    asm volatile("cp.async.wait_group %0;" :: "n"(N) : "memory");
}
__device__ __forceinline__ void ldm_x4(unsigned& r0, unsigned& r1, unsigned& r2, unsigned& r3,
                                       unsigned addr) {
    asm volatile("ldmatrix.sync.aligned.m8n8.x4.shared.b16 {%0,%1,%2,%3}, [%4];"
                 : "=r"(r0), "=r"(r1), "=r"(r2), "=r"(r3) : "r"(addr));
}
__device__ __forceinline__ void mma_f16(float* d, const unsigned* a, const unsigned* b) {
    asm volatile("mma.sync.aligned.m16n8k16.row.col.f32.f16.f16.f32 "
                 "{%0,%1,%2,%3},{%4,%5,%6,%7},{%8,%9},{%0,%1,%2,%3};"
                 : "+f"(d[0]), "+f"(d[1]), "+f"(d[2]), "+f"(d[3])
                 : "r"(a[0]), "r"(a[1]), "r"(a[2]), "r"(a[3]), "r"(b[0]), "r"(b[1]));
}
__device__ __forceinline__ unsigned long long pack2(float lo, float hi) {
    unsigned long long r;
    asm("mov.b64 %0, {%1,%2};" : "=l"(r) : "f"(lo), "f"(hi));
    return r;
}
__device__ __forceinline__ float2 unpack2(unsigned long long v) {
    float2 f;
    asm("mov.b64 {%0,%1}, %2;" : "=f"(f.x), "=f"(f.y) : "l"(v));
    return f;
}
__device__ __forceinline__ void fma2(unsigned long long& a, unsigned long long x,
                                     unsigned long long n) {
    asm("fma.rn.f32x2 %0, %1, %2, %0;" : "+l"(a) : "l"(x), "l"(n));
}

// ================= prep kernels =================
// single edge pass: per-relation degree + bucket store + batch histogram
__global__ void k_build(const int* __restrict__ ei, const int* __restrict__ batch) {
    int i = blockIdx.x * blockDim.x + threadIdx.x;
    if (i < 2 * EE) {
        int r = (i >= EE) ? 1 : 0;
        int e = i - r * EE;
        int s = __ldg(ei + (size_t)r * 2 * EE + e);
        int d = __ldg(ei + (size_t)r * 2 * EE + EE + e);
        atomicAdd(&g_cnt[r * NN + d], 1);
        int pos = atomicAdd(&g_cur[d], 1);
        g_ebuf[(size_t)d * BUCKET + pos] = (unsigned)s | ((unsigned)r << 16);
    } else if (i < 2 * EE + NN) {
        atomicAdd(&g_bcnt[__ldg(batch + i - 2 * EE)], 1);
    }
}

// isd from per-relation degree, restore cnt zero-invariant, zero pool/bcnt
__global__ void k_isd() {
    int i = blockIdx.x * blockDim.x + threadIdx.x;
    if (i < 2 * NN) {
        int c = g_cnt[i];
        g_isd[i] = rsqrtf((float)c + 1.0f);
        g_cnt[i] = 0;                    // restore for next replay
    }
    if (i < GGG * DDD) g_pool[i] = 0.f;
}

// fp16 conversions: features + transposed weights (runs on forked stream)
__global__ void k_cvt(const float* __restrict__ x, const float* __restrict__ W) {
    int i = blockIdx.x * blockDim.x + threadIdx.x;
    if (i < NN * 32) {
        float4 v = ((const float4*)x)[i];
        __half2 a = __floats2half2_rn(v.x, v.y);
        __half2 b = __floats2half2_rn(v.z, v.w);
        ((uint2*)g_h16)[i] = make_uint2(*(unsigned*)&a, *(unsigned*)&b);
    } else if (i < NN * 32 + 2 * 128 * 256) {
        int j = i - NN * 32;
        int l = j >> 15, n = (j >> 8) & 127, k = j & 255;
        int r = k >> 7, kd = k & 127;
        g_w16[j] = __float2half(__ldg(W + (((size_t)(l * 2 + r) * 128 + kd) * 128 + n)));
    }
}

// ================= gather: warp per node, split half-warps, bucket entries =================
__global__ __launch_bounds__(256) void k_gather() {
    int t = blockIdx.x * blockDim.x + threadIdx.x;
    int d    = t >> 5;                 // warp per node
    if (d >= NN) return;
    int lane = t & 31;
    int sub  = lane >> 4;              // 0: even entries, 1: odd entries
    int l16  = lane & 15;              // covers cols l16*8 .. l16*8+7

    unsigned long long a0[4], a1[4];
    unsigned long long z = pack2(0.f, 0.f);
#pragma unroll
    for (int q = 0; q < 4; q++) { a0[q] = z; a1[q] = z; }

    const uint4* h = (const uint4*)g_h16;

    int e0 = d * BUCKET;
    int e1 = e0 + g_cur[d];

#define PROC(v, ent)                                                          \
    {                                                                         \
        const __half2* hp = (const __half2*)&(v);                             \
        float2 f0 = __half22float2(hp[0]);                                    \
        float2 f1 = __half22float2(hp[1]);                                    \
        float2 f2 = __half22float2(hp[2]);                                    \
        float2 f3 = __half22float2(hp[3]);                                    \
        int r_  = ((ent) >> 16) & 1;                                          \
        float nrm = __ldg(g_isd + r_ * NN + ((ent) & 0xFFFF));                \
        float n0_ = r_ ? 0.f : nrm;                                           \
        float n1_ = nrm - n0_;                                                \
        unsigned long long nn0 = pack2(n0_, n0_), nn1 = pack2(n1_, n1_);      \
        unsigned long long x0 = pack2(f0.x, f0.y), x1 = pack2(f1.x, f1.y);    \
        unsigned long long x2 = pack2(f2.x, f2.y), x3 = pack2(f3.x, f3.y);    \
        fma2(a0[0], x0, nn0); fma2(a0[1], x1, nn0);                           \
        fma2(a0[2], x2, nn0); fma2(a0[3], x3, nn0);                           \
        fma2(a1[0], x0, nn1); fma2(a1[1], x1, nn1);                           \
        fma2(a1[2], x2, nn1); fma2(a1[3], x3, nn1);                           \
    }

    int e = e0 + sub;
    for (; e + 2 < e1; e += 4) {
        unsigned ea = g_ebuf[e];
        unsigned eb = g_ebuf[e + 2];
        uint4 va = h[(size_t)(ea & 0xFFFF) * 16 + l16];
        uint4 vb = h[(size_t)(eb & 0xFFFF) * 16 + l16];
        PROC(va, ea);
        PROC(vb, eb);
    }
    if (e < e1) {
        unsigned ea = g_ebuf[e];
        uint4 va = h[(size_t)(ea & 0xFFFF) * 16 + l16];
        PROC(va, ea);
    }
#undef PROC

    // merge the two half-warp partial sums (lane i <-> lane i+16, same l16)
#pragma unroll
    for (int q = 0; q < 4; q++) {
        unsigned long long o0 = __shfl_xor_sync(~0u, a0[q], 16);
        unsigned long long o1 = __shfl_xor_sync(~0u, a1[q], 16);
        float2 A0 = unpack2(a0[q]), B0 = unpack2(o0);
        float2 A1 = unpack2(a1[q]), B1 = unpack2(o1);
        a0[q] = pack2(A0.x + B0.x, A0.y + B0.y);
        a1[q] = pack2(A1.x + B1.x, A1.y + B1.y);
    }

    // self-loop + isd[dst] scaling; sub 0 writes relation-0 block, sub 1 relation-1
    uint4 sv = h[(size_t)d * 16 + l16];
    const __half2* sp = (const __half2*)&sv;
    float2 s0 = __half22float2(sp[0]);
    float2 s1 = __half22float2(sp[1]);
    float2 s2 = __half22float2(sp[2]);
    float2 s3 = __half22float2(sp[3]);
    float hs[8] = {s0.x, s0.y, s1.x, s1.y, s2.x, s2.y, s3.x, s3.y};
    float isd = g_isd[sub * NN + d];
    float isd2 = isd * isd;

    union { uint4 q; __half2 h2[4]; } o;
#pragma unroll
    for (int q = 0; q < 4; q++) {
        float2 A = unpack2(sub ? a1[q] : a0[q]);
        float vx = isd * A.x + isd2 * hs[2 * q];
        float vy = isd * A.y + isd2 * hs[2 * q + 1];
        o.h2[q] = __floats2half2_rn(vx, vy);
    }
    *(uint4*)(g_a16 + (size_t)d * 256 + sub * 128 + l16 * 8) = o.q;
}

// ================= mma.sync fp16 GEMM =================
// smem: buf0 @0 (16KB: A 8K + B 8K), buf1 @16384, bias @32768
#define MMA_SMEM (32768 + 512)

__device__ __forceinline__ void load_chunk(unsigned sbuf, int row0, int kc, int layer, int tid) {
    const __half* wt = g_w16 + (size_t)layer * 32768;
#pragma unroll
    for (int t = 0; t < 4; t++) {
        int cid = tid + t * 256;
        int reg = cid >> 9;             // 0 = A, 1 = B
        int idx = cid & 511;
        int row = idx >> 2;
        int ch  = idx & 3;
        unsigned dst = sbuf + reg * 8192 + row * 64 + ((ch ^ ((row >> 1) & 3)) << 4);
        if (reg == 0) {
            int grow = row0 + row;
            unsigned ok = (grow < NN) ? 16u : 0u;
            int gr = (grow < NN) ? grow : (NN - 1);
            cp16(dst, g_a16 + (size_t)gr * 256 + kc * 32 + ch * 8, ok);
        } else {
            cp16(dst, wt + (size_t)row * 256 + kc * 32 + ch * 8, 16u);
        }
    }
}

__global__ __launch_bounds__(256) void k_mma(const float* __restrict__ bias,
                                             const int* __restrict__ batch,
                                             int layer) {
    extern __shared__ char smem[];
    unsigned sb = smem_u32(smem);
    int tid  = threadIdx.x;
    int lane = tid & 31;
    int wid  = tid >> 5;
    int wm   = wid & 1;
    int wn   = wid >> 1;
    int row0 = blockIdx.x * 128;

    float* bias_s = (float*)(smem + 32768);
    if (tid < 128) bias_s[tid] = __ldg(bias + tid) + __ldg(bias + 128 + tid);

    float acc[4][4][4];
#pragma unroll
    for (int mt = 0; mt < 4; mt++)
#pragma unroll
        for (int nt = 0; nt < 4; nt++)
#pragma unroll
            for (int q = 0; q < 4; q++) acc[mt][nt][q] = 0.f;

    load_chunk(sb, row0, 0, layer, tid);
    cp_commit();

    for (int c = 0; c < 8; c++) {
        if (c + 1 < 8) {
            load_chunk(sb + ((c + 1) & 1) * 16384, row0, c + 1, layer, tid);
            cp_commit();
            cp_wait<1>();
        } else {
            cp_wait<0>();
        }
        __syncthreads();

        unsigned sbuf = sb + (c & 1) * 16384;
#pragma unroll
        for (int s = 0; s < 2; s++) {
            unsigned ah[4][4], bh[4][2];
#pragma unroll
            for (int mt = 0; mt < 4; mt++) {
                int rl = wm * 64 + mt * 16 + ((lane >> 3) & 1) * 8 + (lane & 7);
                int ch = 2 * s + (lane >> 4);
                unsigned ad = sbuf + rl * 64 + ((ch ^ ((rl >> 1) & 3)) << 4);
                ldm_x4(ah[mt][0], ah[mt][1], ah[mt][2], ah[mt][3], ad);
            }
#pragma unroll
            for (int p = 0; p < 2; p++) {
                int rl = wn * 32 + p * 16 + ((lane >> 4) & 1) * 8 + (lane & 7);
                int ch = 2 * s + ((lane >> 3) & 1);
                unsigned bd = sbuf + 8192 + rl * 64 + ((ch ^ ((rl >> 1) & 3)) << 4);
                unsigned r0, r1, r2, r3;
                ldm_x4(r0, r1, r2, r3, bd);
                bh[2 * p][0] = r0;     bh[2 * p][1] = r1;
                bh[2 * p + 1][0] = r2; bh[2 * p + 1][1] = r3;
            }
#pragma unroll
            for (int mt = 0; mt < 4; mt++)
#pragma unroll
                for (int nt = 0; nt < 4; nt++)
                    mma_f16(acc[mt][nt], ah[mt], bh[nt]);
        }
        __syncthreads();
    }

    // ---- epilogue ----
#pragma unroll
    for (int mt = 0; mt < 4; mt++) {
        int gm0 = row0 + wm * 64 + mt * 16 + (lane >> 2);
#pragma unroll
        for (int half = 0; half < 2; half++) {
            int gm = gm0 + half * 8;
            if (gm >= NN) continue;
            if (layer == 0) {
#pragma unroll
                for (int nt = 0; nt < 4; nt++) {
                    int cn = wn * 32 + nt * 8 + (lane & 3) * 2;
                    float v0 = fmaxf(acc[mt][nt][half * 2 + 0] + bias_s[cn], 0.f);
                    float v1 = fmaxf(acc[mt][nt][half * 2 + 1] + bias_s[cn + 1], 0.f);
                    *(__half2*)(g_h16 + (size_t)gm * 128 + cn) = __floats2half2_rn(v0, v1);
                }
            } else {
                int g = __ldg(batch + gm);
#pragma unroll
                for (int nt = 0; nt < 4; nt++) {
                    int cn = wn * 32 + nt * 8 + (lane & 3) * 2;
                    float v0 = acc[mt][nt][half * 2 + 0] + bias_s[cn];
                    float v1 = acc[mt][nt][half * 2 + 1] + bias_s[cn + 1];
                    float* p = g_pool + (size_t)g * 128 + cn;
                    asm volatile("red.global.add.v2.f32 [%0], {%1,%2};"
                                 :: "l"(p), "f"(v0), "f"(v1) : "memory");
                }
            }
        }
    }

    // restore bucket-count zero-invariant after the LAST consumer (layer-1 gather ran before us)
    if (layer == 1) {
        int i = blockIdx.x * 256 + tid;
        if (i < NN) g_cur[i] = 0;
        if (i < GGG) g_bcnt_restore_guard: ;   // (bcnt restored in k_final)
    }
}

// ================= final linear (also restores bcnt zero-invariant) =================
__global__ void k_final(const float* __restrict__ lw, const float* __restrict__ lb,
                        float* __restrict__ out) {
    int tid = threadIdx.x;
    if (tid >= GGG * CCC) return;
    int g = tid >> 3, c = tid & 7;
    float cnt = fmaxf((float)g_bcnt[g], 1.0f);
    float s = 0.f;
#pragma unroll 8
    for (int k = 0; k < DDD; k++)
        s += g_pool[g * DDD + k] * __ldg(lw + k * CCC + c);
    out[tid] = s / cnt + __ldg(lb + c);
    if (c == 0) g_bcnt[g] = 0;   // restore zero-invariant for next replay
}

// ================= launch =================
extern "C" void kernel_launch(void* const* d_in, const int* in_sizes, int n_in,
                              void* d_out, int out_size) {
    const float* x     = (const float*)d_in[0];
    const float* W     = (const float*)d_in[1];
    const float* b     = (const float*)d_in[2];
    const float* lw    = (const float*)d_in[3];
    const float* lb    = (const float*)d_in[4];
    const int*   ei    = (const int*)d_in[5];
    const int*   batch = (const int*)d_in[6];
    float*       out   = (float*)d_out;

    cudaFuncSetAttribute(k_mma, cudaFuncAttributeMaxDynamicSharedMemorySize, MMA_SMEM);

    // fork: fp16 conversions run concurrently with the bucket build
    cudaStream_t s2;
    cudaEvent_t eFork, eJoin;
    cudaStreamCreateWithFlags(&s2, cudaStreamNonBlocking);
    cudaEventCreateWithFlags(&eFork, cudaEventDisableTiming);
    cudaEventCreateWithFlags(&eJoin, cudaEventDisableTiming);

    cudaEventRecord(eFork, 0);
    cudaStreamWaitEvent(s2, eFork, 0);
    k_cvt<<<(NN * 32 + 2 * 128 * 256 + 255) / 256, 256, 0, s2>>>(x, W);
    cudaEventRecord(eJoin, s2);

    // bucket build chain (main stream); cnt/cur arrive zeroed (BSS / self-restored)
    k_build<<<(2 * EE + NN + 255) / 256, 256>>>(ei, batch);
    k_isd<<<(2 * NN + 255) / 256, 256>>>();

    cudaStreamWaitEvent(0, eJoin, 0);

    int mma_blocks = (NN + 127) / 128;
    int gat_blocks = (NN * 32 + 255) / 256;

    // layer 0
    k_gather<<<gat_blocks, 256>>>();
    k_mma<<<mma_blocks, 256, MMA_SMEM>>>(b, batch, 0);

    // layer 1
    k_gather<<<gat_blocks, 256>>>();
    k_mma<<<mma_blocks, 256, MMA_SMEM>>>(b + 2 * DDD, batch, 1);   // also restores g_cur

    // classify (also restores g_bcnt)
    k_final<<<1, 512>>>(lw, lb, out);

    cudaEventDestroy(eFork);
    cudaEventDestroy(eJoin);
    cudaStreamDestroy(s2);
}

// round 14
// speedup vs baseline: 1.0846x; 1.0846x over previous
#include <cuda_runtime.h>
#include <cuda_fp16.h>
#include <cstdint>

#define NN 50000
#define EE 800000
#define DDD 128
#define GGG 64
#define CCC 8

// ---------------- scratch ----------------
__device__ __half    g_h16[NN * DDD];        // fp16 feature table (layer input)
__device__ __half    g_a16[NN * 256];        // aggregated A [node][256] fp16
__device__ __half    g_w16[2 * 128 * 256];   // Wt fp16 [layer][n][k]
__device__ int       g_ecnt[2 * NN];         // INVARIANT: zero at entry & exit
__device__ float     g_isd[2 * NN];
__device__ int       g_off[NN];              // combined CSR offsets
__device__ int       g_cur[NN];              // front cursor (r0); == mid after fill
__device__ int       g_end[NN];              // back cursor (r1); == mid after fill
__device__ int       g_btot[64];
__device__ unsigned  g_ebuf[2 * EE];         // src:16 | fp16(norm)
__device__ int       g_bcnt[GGG];
__device__ float     g_pool[GGG * DDD];

// ================= helpers =================
__device__ __forceinline__ unsigned smem_u32(const void* p) {
    unsigned a;
    asm("{ .reg .u64 t; cvta.to.shared.u64 t, %1; cvt.u32.u64 %0, t; }" : "=r"(a) : "l"(p));
    return a;
}
__device__ __forceinline__ void cp16(unsigned dst, const void* gsrc, unsigned srcsize) {
    asm volatile("cp.async.cg.shared.global [%0], [%1], 16, %2;"
                 :: "r"(dst), "l"(__cvta_generic_to_global((void*)gsrc)), "r"(srcsize) : "memory");
}
__device__ __forceinline__ void cp_commit() { asm volatile("cp.async.commit_group;" ::: "memory"); }
template <int N> __device__ __forceinline__ void cp_wait() {
    asm volatile("cp.async.wait_group %0;" :: "n"(N) : "memory");
}
__device__ __forceinline__ void ldm_x4(unsigned& r0, unsigned& r1, unsigned& r2, unsigned& r3,
                                       unsigned addr) {
    asm volatile("ldmatrix.sync.aligned.m8n8.x4.shared.b16 {%0,%1,%2,%3}, [%4];"
                 : "=r"(r0), "=r"(r1), "=r"(r2), "=r"(r3) : "r"(addr));
}
__device__ __forceinline__ void mma_f16(float* d, const unsigned* a, const unsigned* b) {
    asm volatile("mma.sync.aligned.m16n8k16.row.col.f32.f16.f16.f32 "
                 "{%0,%1,%2,%3},{%4,%5,%6,%7},{%8,%9},{%0,%1,%2,%3};"
                 : "+f"(d[0]), "+f"(d[1]), "+f"(d[2]), "+f"(d[3])
                 : "r"(a[0]), "r"(a[1]), "r"(a[2]), "r"(a[3]), "r"(b[0]), "r"(b[1]));
}
__device__ __forceinline__ unsigned long long pack2(float lo, float hi) {
    unsigned long long r;
    asm("mov.b64 %0, {%1,%2};" : "=l"(r) : "f"(lo), "f"(hi));
    return r;
}
__device__ __forceinline__ float2 unpack2(unsigned long long v) {
    float2 f;
    asm("mov.b64 {%0,%1}, %2;" : "=f"(f.x), "=f"(f.y) : "l"(v));
    return f;
}
__device__ __forceinline__ void fma2(unsigned long long& a, unsigned long long x,
                                     unsigned long long n) {
    asm("fma.rn.f32x2 %0, %1, %2, %0;" : "+l"(a) : "l"(x), "l"(n));
}

// ================= prep kernels =================
__global__ void k_hist(const int* __restrict__ ei) {
    int i = blockIdx.x * blockDim.x + threadIdx.x;
    if (i >= 2 * EE) return;
    int r = (i >= EE) ? 1 : 0;
    int e = i - r * EE;
    int dst = __ldg(ei + (size_t)r * 2 * EE + EE + e);
    atomicAdd(&g_ecnt[r * NN + dst], 1);
}

// scan (combined degree) + isd + pool/bcnt zeroing + ecnt self-restore
__global__ __launch_bounds__(256) void k_scanA() {
    __shared__ int sm[256];
    int bx = blockIdx.x, t = threadIdx.x;
    int gi = bx * 256 + t;
    if (gi < GGG * DDD) g_pool[gi] = 0.f;
    if (gi < GGG) g_bcnt[gi] = 0;
    int base = bx * 1024 + t * 4;
    int c[4];
#pragma unroll
    for (int j = 0; j < 4; j++) {
        int n = base + j;
        if (n < NN) {
            int c0 = g_ecnt[n], c1 = g_ecnt[NN + n];
            g_isd[n]      = rsqrtf((float)c0 + 1.0f);
            g_isd[NN + n] = rsqrtf((float)c1 + 1.0f);
            g_ecnt[n] = 0;            // restore zero-invariant for next replay
            g_ecnt[NN + n] = 0;
            c[j] = c0 + c1;
        } else c[j] = 0;
    }
    int s = c[0] + c[1] + c[2] + c[3];
    sm[t] = s;
    __syncthreads();
#pragma unroll
    for (int o = 1; o < 256; o <<= 1) {
        int v = (t >= o) ? sm[t - o] : 0;
        __syncthreads();
        sm[t] += v;
        __syncthreads();
    }
    int p = sm[t] - s;
#pragma unroll
    for (int j = 0; j < 4; j++) {
        int n = base + j;
        if (n < NN) {
            g_off[n] = p;             // local exclusive prefix
            g_end[n] = p + c[j];      // local end (boff added in scanC)
        }
        p += c[j];
    }
    if (t == 255) g_btot[bx] = sm[255];
}

// scanC with built-in block-offset reduction; finalizes off/cur/end
__global__ __launch_bounds__(256) void k_scanC() {
    __shared__ int wsum[8];
    __shared__ int boff_s;
    int bx = blockIdx.x, t = threadIdx.x;
    int v = (t < bx) ? g_btot[t] : 0;
#pragma unroll
    for (int o = 16; o; o >>= 1) v += __shfl_down_sync(~0u, v, o);
    if ((t & 31) == 0) wsum[t >> 5] = v;
    __syncthreads();
    if (t == 0) {
        int s = 0;
#pragma unroll
        for (int w = 0; w < 8; w++) s += wsum[w];
        boff_s = s;
    }
    __syncthreads();
    int boff = boff_s;
    int base = bx * 1024 + t * 4;
#pragma unroll
    for (int j = 0; j < 4; j++) {
        int n = base + j;
        if (n < NN) {
            int o = g_off[n] + boff;
            g_off[n] = o;
            g_cur[n] = o;              // r0 fills forward from here
            g_end[n] += boff;          // r1 fills backward from here
        }
    }
}

// edge fill: relation-partitioned (r0 forward, r1 backward) + batch histogram
__global__ void k_fill(const int* __restrict__ ei, const int* __restrict__ batch) {
    int i = blockIdx.x * blockDim.x + threadIdx.x;
    if (i < 2 * EE) {
        int r = (i >= EE) ? 1 : 0;
        int e = i - r * EE;
        int s = __ldg(ei + (size_t)r * 2 * EE + e);
        int d = __ldg(ei + (size_t)r * 2 * EE + EE + e);
        float nrm = g_isd[r * NN + s];
        unsigned hb = (unsigned)__half_as_ushort(__float2half(nrm));
        unsigned ent = (unsigned)s | (hb << 16);
        int pos = (r == 0) ? atomicAdd(&g_cur[d], 1)
                           : (atomicSub(&g_end[d], 1) - 1);
        g_ebuf[pos] = ent;
    } else if (i < 2 * EE + NN) {
        atomicAdd(&g_bcnt[__ldg(batch + i - 2 * EE)], 1);
    }
}

// fp16 conversions: features + transposed weights (runs on forked stream)
__global__ void k_cvt(const float* __restrict__ x, const float* __restrict__ W) {
    int i = blockIdx.x * blockDim.x + threadIdx.x;
    if (i < NN * 32) {
        float4 v = ((const float4*)x)[i];
        __half2 a = __floats2half2_rn(v.x, v.y);
        __half2 b = __floats2half2_rn(v.z, v.w);
        ((uint2*)g_h16)[i] = make_uint2(*(unsigned*)&a, *(unsigned*)&b);
    } else if (i < NN * 32 + 2 * 128 * 256) {
        int j = i - NN * 32;
        int l = j >> 15, n = (j >> 8) & 127, k = j & 255;
        int r = k >> 7, kd = k & 127;
        g_w16[j] = __float2half(__ldg(W + (((size_t)(l * 2 + r) * 128 + kd) * 128 + n)));
    }
}

// ================= gather: warp per node, split half-warps, relation-partitioned =================
__global__ __launch_bounds__(256) void k_gather() {
    int t = blockIdx.x * blockDim.x + threadIdx.x;
    int d    = t >> 5;                 // warp per node
    if (d >= NN) return;
    int lane = t & 31;
    int sub  = lane >> 4;              // 0: even entries, 1: odd entries
    int l16  = lane & 15;              // covers cols l16*8 .. l16*8+7

    unsigned long long a0[4], a1[4];
    unsigned long long z = pack2(0.f, 0.f);
#pragma unroll
    for (int q = 0; q < 4; q++) { a0[q] = z; a1[q] = z; }

    const uint4* h = (const uint4*)g_h16;

    int e0  = g_off[d];
    int mid = g_cur[d];                // post-fill meeting point: off + deg0
    int e1  = (d < NN - 1) ? g_off[d + 1] : 2 * EE;

#define PROC(v, ent, acc)                                                     \
    {                                                                         \
        const __half2* hp = (const __half2*)&(v);                             \
        float2 f0 = __half22float2(hp[0]);                                    \
        float2 f1 = __half22float2(hp[1]);                                    \
        float2 f2 = __half22float2(hp[2]);                                    \
        float2 f3 = __half22float2(hp[3]);                                    \
        float nrm = __half2float(__ushort_as_half(                            \
                        (unsigned short)((ent) >> 16)));                      \
        unsigned long long nn = pack2(nrm, nrm);                              \
        fma2((acc)[0], pack2(f0.x, f0.y), nn);                                \
        fma2((acc)[1], pack2(f1.x, f1.y), nn);                                \
        fma2((acc)[2], pack2(f2.x, f2.y), nn);                                \
        fma2((acc)[3], pack2(f3.x, f3.y), nn);                                \
    }

    // relation-0 edges: [e0, mid)
    int e = e0 + sub;
    for (; e + 2 < mid; e += 4) {
        unsigned ea = g_ebuf[e];
        unsigned eb = g_ebuf[e + 2];
        uint4 va = h[(size_t)(ea & 0xFFFF) * 16 + l16];
        uint4 vb = h[(size_t)(eb & 0xFFFF) * 16 + l16];
        PROC(va, ea, a0);
        PROC(vb, eb, a0);
    }
    if (e < mid) {
        unsigned ea = g_ebuf[e];
        uint4 va = h[(size_t)(ea & 0xFFFF) * 16 + l16];
        PROC(va, ea, a0);
    }
    // relation-1 edges: [mid, e1)
    e = mid + sub;
    for (; e + 2 < e1; e += 4) {
        unsigned ea = g_ebuf[e];
        unsigned eb = g_ebuf[e + 2];
        uint4 va = h[(size_t)(ea & 0xFFFF) * 16 + l16];
        uint4 vb = h[(size_t)(eb & 0xFFFF) * 16 + l16];
        PROC(va, ea, a1);
        PROC(vb, eb, a1);
    }
    if (e < e1) {
        unsigned ea = g_ebuf[e];
        uint4 va = h[(size_t)(ea & 0xFFFF) * 16 + l16];
        PROC(va, ea, a1);
    }
#undef PROC

    // merge the two half-warp partial sums (lane i <-> lane i+16, same l16)
#pragma unroll
    for (int q = 0; q < 4; q++) {
        unsigned long long o0 = __shfl_xor_sync(~0u, a0[q], 16);
        unsigned long long o1 = __shfl_xor_sync(~0u, a1[q], 16);
        float2 A0 = unpack2(a0[q]), B0 = unpack2(o0);
        float2 A1 = unpack2(a1[q]), B1 = unpack2(o1);
        a0[q] = pack2(A0.x + B0.x, A0.y + B0.y);
        a1[q] = pack2(A1.x + B1.x, A1.y + B1.y);
    }

    // self-loop + isd[dst] scaling; sub 0 writes relation-0 block, sub 1 relation-1
    uint4 sv = h[(size_t)d * 16 + l16];
    const __half2* sp = (const __half2*)&sv;
    float2 s0 = __half22float2(sp[0]);
    float2 s1 = __half22float2(sp[1]);
    float2 s2 = __half22float2(sp[2]);
    float2 s3 = __half22float2(sp[3]);
    float hs[8] = {s0.x, s0.y, s1.x, s1.y, s2.x, s2.y, s3.x, s3.y};
    float isd = g_isd[sub * NN + d];
    float isd2 = isd * isd;

    union { uint4 q; __half2 h2[4]; } o;
#pragma unroll
    for (int q = 0; q < 4; q++) {
        float2 A = unpack2(sub ? a1[q] : a0[q]);
        float vx = isd * A.x + isd2 * hs[2 * q];
        float vy = isd * A.y + isd2 * hs[2 * q + 1];
        o.h2[q] = __floats2half2_rn(vx, vy);
    }
    *(uint4*)(g_a16 + (size_t)d * 256 + sub * 128 + l16 * 8) = o.q;
}

// ================= mma.sync fp16 GEMM =================
// smem: buf0 @0 (16KB: A 8K + B 8K), buf1 @16384, bias @32768
#define MMA_SMEM (32768 + 512)

__device__ __forceinline__ void load_chunk(unsigned sbuf, int row0, int kc, int layer, int tid) {
    const __half* wt = g_w16 + (size_t)layer * 32768;
#pragma unroll
    for (int t = 0; t < 4; t++) {
        int cid = tid + t * 256;
        int reg = cid >> 9;             // 0 = A, 1 = B
        int idx = cid & 511;
        int row = idx >> 2;
        int ch  = idx & 3;
        unsigned dst = sbuf + reg * 8192 + row * 64 + ((ch ^ ((row >> 1) & 3)) << 4);
        if (reg == 0) {
            int grow = row0 + row;
            unsigned ok = (grow < NN) ? 16u : 0u;
            int gr = (grow < NN) ? grow : (NN - 1);
            cp16(dst, g_a16 + (size_t)gr * 256 + kc * 32 + ch * 8, ok);
        } else {
            cp16(dst, wt + (size_t)row * 256 + kc * 32 + ch * 8, 16u);
        }
    }
}

__global__ __launch_bounds__(256) void k_mma(const float* __restrict__ bias,
                                             const int* __restrict__ batch,
                                             int layer) {
    extern __shared__ char smem[];
    unsigned sb = smem_u32(smem);
    int tid  = threadIdx.x;
    int lane = tid & 31;
    int wid  = tid >> 5;
    int wm   = wid & 1;
    int wn   = wid >> 1;
    int row0 = blockIdx.x * 128;

    float* bias_s = (float*)(smem + 32768);
    if (tid < 128) bias_s[tid] = __ldg(bias + tid) + __ldg(bias + 128 + tid);

    float acc[4][4][4];
#pragma unroll
    for (int mt = 0; mt < 4; mt++)
#pragma unroll
        for (int nt = 0; nt < 4; nt++)
#pragma unroll
            for (int q = 0; q < 4; q++) acc[mt][nt][q] = 0.f;

    load_chunk(sb, row0, 0, layer, tid);
    cp_commit();

    for (int c = 0; c < 8; c++) {
        if (c + 1 < 8) {
            load_chunk(sb + ((c + 1) & 1) * 16384, row0, c + 1, layer, tid);
            cp_commit();
            cp_wait<1>();
        } else {
            cp_wait<0>();
        }
        __syncthreads();

        unsigned sbuf = sb + (c & 1) * 16384;
#pragma unroll
        for (int s = 0; s < 2; s++) {
            unsigned ah[4][4], bh[4][2];
#pragma unroll
            for (int mt = 0; mt < 4; mt++) {
                int rl = wm * 64 + mt * 16 + ((lane >> 3) & 1) * 8 + (lane & 7);
                int ch = 2 * s + (lane >> 4);
                unsigned ad = sbuf + rl * 64 + ((ch ^ ((rl >> 1) & 3)) << 4);
                ldm_x4(ah[mt][0], ah[mt][1], ah[mt][2], ah[mt][3], ad);
            }
#pragma unroll
            for (int p = 0; p < 2; p++) {
                int rl = wn * 32 + p * 16 + ((lane >> 4) & 1) * 8 + (lane & 7);
                int ch = 2 * s + ((lane >> 3) & 1);
                unsigned bd = sbuf + 8192 + rl * 64 + ((ch ^ ((rl >> 1) & 3)) << 4);
                unsigned r0, r1, r2, r3;
                ldm_x4(r0, r1, r2, r3, bd);
                bh[2 * p][0] = r0;     bh[2 * p][1] = r1;
                bh[2 * p + 1][0] = r2; bh[2 * p + 1][1] = r3;
            }
#pragma unroll
            for (int mt = 0; mt < 4; mt++)
#pragma unroll
                for (int nt = 0; nt < 4; nt++)
                    mma_f16(acc[mt][nt], ah[mt], bh[nt]);
        }
        __syncthreads();
    }

    // ---- epilogue ----
#pragma unroll
    for (int mt = 0; mt < 4; mt++) {
        int gm0 = row0 + wm * 64 + mt * 16 + (lane >> 2);
#pragma unroll
        for (int half = 0; half < 2; half++) {
            int gm = gm0 + half * 8;
            if (gm >= NN) continue;
            if (layer == 0) {
#pragma unroll
                for (int nt = 0; nt < 4; nt++) {
                    int cn = wn * 32 + nt * 8 + (lane & 3) * 2;
                    float v0 = fmaxf(acc[mt][nt][half * 2 + 0] + bias_s[cn], 0.f);
                    float v1 = fmaxf(acc[mt][nt][half * 2 + 1] + bias_s[cn + 1], 0.f);
                    *(__half2*)(g_h16 + (size_t)gm * 128 + cn) = __floats2half2_rn(v0, v1);
                }
            } else {
                int g = __ldg(batch + gm);
#pragma unroll
                for (int nt = 0; nt < 4; nt++) {
                    int cn = wn * 32 + nt * 8 + (lane & 3) * 2;
                    float v0 = acc[mt][nt][half * 2 + 0] + bias_s[cn];
                    float v1 = acc[mt][nt][half * 2 + 1] + bias_s[cn + 1];
                    float* p = g_pool + (size_t)g * 128 + cn;
                    asm volatile("red.global.add.v2.f32 [%0], {%1,%2};"
                                 :: "l"(p), "f"(v0), "f"(v1) : "memory");
                }
            }
        }
    }
}

// ================= final linear =================
__global__ void k_final(const float* __restrict__ lw, const float* __restrict__ lb,
                        float* __restrict__ out) {
    int tid = threadIdx.x;
    if (tid >= GGG * CCC) return;
    int g = tid >> 3, c = tid & 7;
    float cnt = fmaxf((float)g_bcnt[g], 1.0f);
    float s = 0.f;
#pragma unroll 8
    for (int k = 0; k < DDD; k++)
        s += g_pool[g * DDD + k] * __ldg(lw + k * CCC + c);
    out[tid] = s / cnt + __ldg(lb + c);
}

// ================= launch =================
extern "C" void kernel_launch(void* const* d_in, const int* in_sizes, int n_in,
                              void* d_out, int out_size) {
    const float* x     = (const float*)d_in[0];
    const float* W     = (const float*)d_in[1];
    const float* b     = (const float*)d_in[2];
    const float* lw    = (const float*)d_in[3];
    const float* lb    = (const float*)d_in[4];
    const int*   ei    = (const int*)d_in[5];
    const int*   batch = (const int*)d_in[6];
    float*       out   = (float*)d_out;

    cudaFuncSetAttribute(k_mma, cudaFuncAttributeMaxDynamicSharedMemorySize, MMA_SMEM);

    // fork: fp16 conversions run concurrently with the CSR build
    cudaStream_t s2;
    cudaEvent_t eFork, eJoin;
    cudaStreamCreateWithFlags(&s2, cudaStreamNonBlocking);
    cudaEventCreateWithFlags(&eFork, cudaEventDisableTiming);
    cudaEventCreateWithFlags(&eJoin, cudaEventDisableTiming);

    cudaEventRecord(eFork, 0);
    cudaStreamWaitEvent(s2, eFork, 0);
    k_cvt<<<(NN * 32 + 2 * 128 * 256 + 255) / 256, 256, 0, s2>>>(x, W);
    cudaEventRecord(eJoin, s2);

    // CSR build chain (main stream); ecnt arrives zeroed (BSS / self-restored)
    k_hist<<<(2 * EE + 255) / 256, 256>>>(ei);
    k_scanA<<<49, 256>>>();
    k_scanC<<<49, 256>>>();
    k_fill<<<(2 * EE + NN + 255) / 256, 256>>>(ei, batch);

    cudaStreamWaitEvent(0, eJoin, 0);

    int mma_blocks = (NN + 127) / 128;
    int gat_blocks = (NN * 32 + 255) / 256;

    // layer 0
    k_gather<<<gat_blocks, 256>>>();
    k_mma<<<mma_blocks, 256, MMA_SMEM>>>(b, batch, 0);

    // layer 1
    k_gather<<<gat_blocks, 256>>>();
    k_mma<<<mma_blocks, 256, MMA_SMEM>>>(b + 2 * DDD, batch, 1);

    // classify
    k_final<<<1, 512>>>(lw, lb, out);

    cudaEventDestroy(eFork);
    cudaEventDestroy(eJoin);
    cudaStreamDestroy(s2);
}

// round 15
// speedup vs baseline: 1.1008x; 1.0149x over previous
#include <cuda_runtime.h>
#include <cuda_fp16.h>
#include <cstdint>

#define NN 50000
#define EE 800000
#define DDD 128
#define GGG 64
#define CCC 8

// ---------------- scratch ----------------
__device__ __half    g_h16[NN * DDD];        // fp16 feature table (layer input)
__device__ __half    g_a16[NN * 256];        // aggregated A [node][256] fp16
__device__ __half    g_w16[2 * 128 * 256];   // Wt fp16 [layer][n][k]
__device__ int       g_ecnt[2 * NN];
__device__ float     g_isd[2 * NN];
__device__ int       g_off[NN];
__device__ int       g_cur[NN];
__device__ int       g_btot[64];
__device__ unsigned  g_ebuf[2 * EE];         // src:16 | fp16(norm) w/ sign=relation
__device__ int       g_bcnt[GGG];
__device__ float     g_pool[GGG * DDD];

// ================= helpers =================
__device__ __forceinline__ unsigned smem_u32(const void* p) {
    unsigned a;
    asm("{ .reg .u64 t; cvta.to.shared.u64 t, %1; cvt.u32.u64 %0, t; }" : "=r"(a) : "l"(p));
    return a;
}
__device__ __forceinline__ void cp16(unsigned dst, const void* gsrc, unsigned srcsize) {
    asm volatile("cp.async.cg.shared.global [%0], [%1], 16, %2;"
                 :: "r"(dst), "l"(__cvta_generic_to_global((void*)gsrc)), "r"(srcsize) : "memory");
}
__device__ __forceinline__ void cp_commit() { asm volatile("cp.async.commit_group;" ::: "memory"); }
template <int N> __device__ __forceinline__ void cp_wait() {
    asm volatile("cp.async.wait_group %0;" :: "n"(N) : "memory");
}
__device__ __forceinline__ void ldm_x4(unsigned& r0, unsigned& r1, unsigned& r2, unsigned& r3,
                                       unsigned addr) {
    asm volatile("ldmatrix.sync.aligned.m8n8.x4.shared.b16 {%0,%1,%2,%3}, [%4];"
                 : "=r"(r0), "=r"(r1), "=r"(r2), "=r"(r3) : "r"(addr));
}
__device__ __forceinline__ void mma_f16(float* d, const unsigned* a, const unsigned* b) {
    asm volatile("mma.sync.aligned.m16n8k16.row.col.f32.f16.f16.f32 "
                 "{%0,%1,%2,%3},{%4,%5,%6,%7},{%8,%9},{%0,%1,%2,%3};"
                 : "+f"(d[0]), "+f"(d[1]), "+f"(d[2]), "+f"(d[3])
                 : "r"(a[0]), "r"(a[1]), "r"(a[2]), "r"(a[3]), "r"(b[0]), "r"(b[1]));
}
__device__ __forceinline__ unsigned long long pack2(float lo, float hi) {
    unsigned long long r;
    asm("mov.b64 %0, {%1,%2};" : "=l"(r) : "f"(lo), "f"(hi));
    return r;
}
__device__ __forceinline__ float2 unpack2(unsigned long long v) {
    float2 f;
    asm("mov.b64 {%0,%1}, %2;" : "=f"(f.x), "=f"(f.y) : "l"(v));
    return f;
}
__device__ __forceinline__ void fma2(unsigned long long& a, unsigned long long x,
                                     unsigned long long n) {
    asm("fma.rn.f32x2 %0, %1, %2, %0;" : "+l"(a) : "l"(x), "l"(n));
}

// ================= prep kernels =================
__global__ void k_zero() {
    int i = blockIdx.x * blockDim.x + threadIdx.x;
    if (i < 2 * NN) g_ecnt[i] = 0;
}

__global__ void k_hist(const int* __restrict__ ei) {
    int i = blockIdx.x * blockDim.x + threadIdx.x;
    if (i >= 2 * EE) return;
    int r = (i >= EE) ? 1 : 0;
    int e = i - r * EE;
    int dst = __ldg(ei + (size_t)r * 2 * EE + EE + e);
    atomicAdd(&g_ecnt[r * NN + dst], 1);
}

// scan (combined degree) + isd + pool/bcnt zeroing
__global__ __launch_bounds__(256) void k_scanA() {
    __shared__ int sm[256];
    int bx = blockIdx.x, t = threadIdx.x;
    int gi = bx * 256 + t;
    if (gi < GGG * DDD) g_pool[gi] = 0.f;
    if (gi < GGG) g_bcnt[gi] = 0;
    int base = bx * 1024 + t * 4;
    int c[4];
#pragma unroll
    for (int j = 0; j < 4; j++) {
        int n = base + j;
        if (n < NN) {
            int c0 = g_ecnt[n], c1 = g_ecnt[NN + n];
            g_isd[n]      = rsqrtf((float)c0 + 1.0f);
            g_isd[NN + n] = rsqrtf((float)c1 + 1.0f);
            c[j] = c0 + c1;
        } else c[j] = 0;
    }
    int s = c[0] + c[1] + c[2] + c[3];
    sm[t] = s;
    __syncthreads();
#pragma unroll
    for (int o = 1; o < 256; o <<= 1) {
        int v = (t >= o) ? sm[t - o] : 0;
        __syncthreads();
        sm[t] += v;
        __syncthreads();
    }
    int p = sm[t] - s;
#pragma unroll
    for (int j = 0; j < 4; j++) {
        int n = base + j;
        if (n < NN) g_off[n] = p;
        p += c[j];
    }
    if (t == 255) g_btot[bx] = sm[255];
}

// scanC with built-in block-offset reduction
__global__ __launch_bounds__(256) void k_scanC() {
    __shared__ int wsum[8];
    __shared__ int boff_s;
    int bx = blockIdx.x, t = threadIdx.x;
    int v = (t < bx) ? g_btot[t] : 0;
#pragma unroll
    for (int o = 16; o; o >>= 1) v += __shfl_down_sync(~0u, v, o);
    if ((t & 31) == 0) wsum[t >> 5] = v;
    __syncthreads();
    if (t == 0) {
        int s = 0;
#pragma unroll
        for (int w = 0; w < 8; w++) s += wsum[w];
        boff_s = s;
    }
    __syncthreads();
    int boff = boff_s;
    int base = bx * 1024 + t * 4;
#pragma unroll
    for (int j = 0; j < 4; j++) {
        int n = base + j;
        if (n < NN) {
            int o = g_off[n] + boff;
            g_off[n] = o;
            g_cur[n] = o;
        }
    }
}

// edge fill (packed 4B entries) + batch histogram
__global__ void k_fill(const int* __restrict__ ei, const int* __restrict__ batch) {
    int i = blockIdx.x * blockDim.x + threadIdx.x;
    if (i < 2 * EE) {
        int r = (i >= EE) ? 1 : 0;
        int e = i - r * EE;
        int s = __ldg(ei + (size_t)r * 2 * EE + e);
        int d = __ldg(ei + (size_t)r * 2 * EE + EE + e);
        float nrm = g_isd[r * NN + s];
        unsigned hb = (unsigned)__half_as_ushort(__float2half(nrm)) | ((unsigned)r << 15);
        unsigned ent = (unsigned)s | (hb << 16);
        int pos = atomicAdd(&g_cur[d], 1);
        g_ebuf[pos] = ent;
    } else if (i < 2 * EE + NN) {
        atomicAdd(&g_bcnt[__ldg(batch + i - 2 * EE)], 1);
    }
}

// fp16 conversions: features + transposed weights (runs on forked stream)
__global__ void k_cvt(const float* __restrict__ x, const float* __restrict__ W) {
    int i = blockIdx.x * blockDim.x + threadIdx.x;
    if (i < NN * 32) {
        float4 v = ((const float4*)x)[i];
        __half2 a = __floats2half2_rn(v.x, v.y);
        __half2 b = __floats2half2_rn(v.z, v.w);
        ((uint2*)g_h16)[i] = make_uint2(*(unsigned*)&a, *(unsigned*)&b);
    } else if (i < NN * 32 + 2 * 128 * 256) {
        int j = i - NN * 32;
        int l = j >> 15, n = (j >> 8) & 127, k = j & 255;
        int r = k >> 7, kd = k & 127;
        g_w16[j] = __float2half(__ldg(W + (((size_t)(l * 2 + r) * 128 + kd) * 128 + n)));
    }
}

// ================= gather: warp per node, split half-warps =================
// launch_bounds(256, 6): cap regs ~42 -> 6 blocks/SM (48 warps) for latency hiding
__global__ __launch_bounds__(256, 6) void k_gather() {
    int t = blockIdx.x * blockDim.x + threadIdx.x;
    int d    = t >> 5;                 // warp per node
    if (d >= NN) return;
    int lane = t & 31;
    int sub  = lane >> 4;              // 0: even edges, 1: odd edges
    int l16  = lane & 15;              // covers cols l16*8 .. l16*8+7

    unsigned long long a0[4], a1[4];
    unsigned long long z = pack2(0.f, 0.f);
#pragma unroll
    for (int q = 0; q < 4; q++) { a0[q] = z; a1[q] = z; }

    const uint4* h = (const uint4*)g_h16;

    int e0 = g_off[d];
    int e1 = (d < NN - 1) ? g_off[d + 1] : 2 * EE;

#define PROC(v, ent)                                                          \
    {                                                                         \
        const __half2* hp = (const __half2*)&(v);                             \
        float2 f0 = __half22float2(hp[0]);                                    \
        float2 f1 = __half22float2(hp[1]);                                    \
        float2 f2 = __half22float2(hp[2]);                                    \
        float2 f3 = __half22float2(hp[3]);                                    \
        float nrm = __half2float(__ushort_as_half(                            \
                        (unsigned short)(((ent) >> 16) & 0x7FFF)));           \
        float n0_ = ((ent) & 0x80000000u) ? 0.f : nrm;                        \
        float n1_ = nrm - n0_;                                                \
        unsigned long long nn0 = pack2(n0_, n0_), nn1 = pack2(n1_, n1_);      \
        unsigned long long x0 = pack2(f0.x, f0.y), x1 = pack2(f1.x, f1.y);    \
        unsigned long long x2 = pack2(f2.x, f2.y), x3 = pack2(f3.x, f3.y);    \
        fma2(a0[0], x0, nn0); fma2(a0[1], x1, nn0);                           \
        fma2(a0[2], x2, nn0); fma2(a0[3], x3, nn0);                           \
        fma2(a1[0], x0, nn1); fma2(a1[1], x1, nn1);                           \
        fma2(a1[2], x2, nn1); fma2(a1[3], x3, nn1);                           \
    }

    int e = e0 + sub;
    for (; e + 2 < e1; e += 4) {
        unsigned ea = g_ebuf[e];
        unsigned eb = g_ebuf[e + 2];
        uint4 va = h[(size_t)(ea & 0xFFFF) * 16 + l16];
        uint4 vb = h[(size_t)(eb & 0xFFFF) * 16 + l16];
        PROC(va, ea);
        PROC(vb, eb);
    }
    if (e < e1) {
        unsigned ea = g_ebuf[e];
        uint4 va = h[(size_t)(ea & 0xFFFF) * 16 + l16];
        PROC(va, ea);
    }
#undef PROC

    // merge the two half-warp partial sums (lane i <-> lane i+16, same l16)
#pragma unroll
    for (int q = 0; q < 4; q++) {
        unsigned long long o0 = __shfl_xor_sync(~0u, a0[q], 16);
        unsigned long long o1 = __shfl_xor_sync(~0u, a1[q], 16);
        float2 A0 = unpack2(a0[q]), B0 = unpack2(o0);
        float2 A1 = unpack2(a1[q]), B1 = unpack2(o1);
        a0[q] = pack2(A0.x + B0.x, A0.y + B0.y);
        a1[q] = pack2(A1.x + B1.x, A1.y + B1.y);
    }

    // self-loop + isd[dst] scaling; sub 0 writes relation-0 block, sub 1 relation-1
    uint4 sv = h[(size_t)d * 16 + l16];
    const __half2* sp = (const __half2*)&sv;
    float2 s0 = __half22float2(sp[0]);
    float2 s1 = __half22float2(sp[1]);
    float2 s2 = __half22float2(sp[2]);
    float2 s3 = __half22float2(sp[3]);
    float hs[8] = {s0.x, s0.y, s1.x, s1.y, s2.x, s2.y, s3.x, s3.y};
    float isd = g_isd[sub * NN + d];
    float isd2 = isd * isd;

    union { uint4 q; __half2 h2[4]; } o;
#pragma unroll
    for (int q = 0; q < 4; q++) {
        float2 A = unpack2(sub ? a1[q] : a0[q]);
        float vx = isd * A.x + isd2 * hs[2 * q];
        float vy = isd * A.y + isd2 * hs[2 * q + 1];
        o.h2[q] = __floats2half2_rn(vx, vy);
    }
    *(uint4*)(g_a16 + (size_t)d * 256 + sub * 128 + l16 * 8) = o.q;
}

// ================= mma.sync fp16 GEMM =================
// smem: buf0 @0 (16KB: A 8K + B 8K), buf1 @16384, bias @32768
#define MMA_SMEM (32768 + 512)

__device__ __forceinline__ void load_chunk(unsigned sbuf, int row0, int kc, int layer, int tid) {
    const __half* wt = g_w16 + (size_t)layer * 32768;
#pragma unroll
    for (int t = 0; t < 4; t++) {
        int cid = tid + t * 256;
        int reg = cid >> 9;             // 0 = A, 1 = B
        int idx = cid & 511;
        int row = idx >> 2;
        int ch  = idx & 3;
        unsigned dst = sbuf + reg * 8192 + row * 64 + ((ch ^ ((row >> 1) & 3)) << 4);
        if (reg == 0) {
            int grow = row0 + row;
            unsigned ok = (grow < NN) ? 16u : 0u;
            int gr = (grow < NN) ? grow : (NN - 1);
            cp16(dst, g_a16 + (size_t)gr * 256 + kc * 32 + ch * 8, ok);
        } else {
            cp16(dst, wt + (size_t)row * 256 + kc * 32 + ch * 8, 16u);
        }
    }
}

__global__ __launch_bounds__(256) void k_mma(const float* __restrict__ bias,
                                             const int* __restrict__ batch,
                                             int layer) {
    extern __shared__ char smem[];
    unsigned sb = smem_u32(smem);
    int tid  = threadIdx.x;
    int lane = tid & 31;
    int wid  = tid >> 5;
    int wm   = wid & 1;
    int wn   = wid >> 1;
    int row0 = blockIdx.x * 128;

    float* bias_s = (float*)(smem + 32768);
    if (tid < 128) bias_s[tid] = __ldg(bias + tid) + __ldg(bias + 128 + tid);

    float acc[4][4][4];
#pragma unroll
    for (int mt = 0; mt < 4; mt++)
#pragma unroll
        for (int nt = 0; nt < 4; nt++)
#pragma unroll
            for (int q = 0; q < 4; q++) acc[mt][nt][q] = 0.f;

    load_chunk(sb, row0, 0, layer, tid);
    cp_commit();

    for (int c = 0; c < 8; c++) {
        if (c + 1 < 8) {
            load_chunk(sb + ((c + 1) & 1) * 16384, row0, c + 1, layer, tid);
            cp_commit();
            cp_wait<1>();
        } else {
            cp_wait<0>();
        }
        __syncthreads();

        unsigned sbuf = sb + (c & 1) * 16384;
#pragma unroll
        for (int s = 0; s < 2; s++) {
            unsigned ah[4][4], bh[4][2];
#pragma unroll
            for (int mt = 0; mt < 4; mt++) {
                int rl = wm * 64 + mt * 16 + ((lane >> 3) & 1) * 8 + (lane & 7);
                int ch = 2 * s + (lane >> 4);
                unsigned ad = sbuf + rl * 64 + ((ch ^ ((rl >> 1) & 3)) << 4);
                ldm_x4(ah[mt][0], ah[mt][1], ah[mt][2], ah[mt][3], ad);
            }
#pragma unroll
            for (int p = 0; p < 2; p++) {
                int rl = wn * 32 + p * 16 + ((lane >> 4) & 1) * 8 + (lane & 7);
                int ch = 2 * s + ((lane >> 3) & 1);
                unsigned bd = sbuf + 8192 + rl * 64 + ((ch ^ ((rl >> 1) & 3)) << 4);
                unsigned r0, r1, r2, r3;
                ldm_x4(r0, r1, r2, r3, bd);
                bh[2 * p][0] = r0;     bh[2 * p][1] = r1;
                bh[2 * p + 1][0] = r2; bh[2 * p + 1][1] = r3;
            }
#pragma unroll
            for (int mt = 0; mt < 4; mt++)
#pragma unroll
                for (int nt = 0; nt < 4; nt++)
                    mma_f16(acc[mt][nt], ah[mt], bh[nt]);
        }
        __syncthreads();
    }

    // ---- epilogue ----
#pragma unroll
    for (int mt = 0; mt < 4; mt++) {
        int gm0 = row0 + wm * 64 + mt * 16 + (lane >> 2);
#pragma unroll
        for (int half = 0; half < 2; half++) {
            int gm = gm0 + half * 8;
            if (gm >= NN) continue;
            if (layer == 0) {
#pragma unroll
                for (int nt = 0; nt < 4; nt++) {
                    int cn = wn * 32 + nt * 8 + (lane & 3) * 2;
                    float v0 = fmaxf(acc[mt][nt][half * 2 + 0] + bias_s[cn], 0.f);
                    float v1 = fmaxf(acc[mt][nt][half * 2 + 1] + bias_s[cn + 1], 0.f);
                    *(__half2*)(g_h16 + (size_t)gm * 128 + cn) = __floats2half2_rn(v0, v1);
                }
            } else {
                int g = __ldg(batch + gm);
#pragma unroll
                for (int nt = 0; nt < 4; nt++) {
                    int cn = wn * 32 + nt * 8 + (lane & 3) * 2;
                    float v0 = acc[mt][nt][half * 2 + 0] + bias_s[cn];
                    float v1 = acc[mt][nt][half * 2 + 1] + bias_s[cn + 1];
                    float* p = g_pool + (size_t)g * 128 + cn;
                    asm volatile("red.global.add.v2.f32 [%0], {%1,%2};"
                                 :: "l"(p), "f"(v0), "f"(v1) : "memory");
                }
            }
        }
    }
}

// ================= final linear =================
__global__ void k_final(const float* __restrict__ lw, const float* __restrict__ lb,
                        float* __restrict__ out) {
    int tid = threadIdx.x;
    if (tid >= GGG * CCC) return;
    int g = tid >> 3, c = tid & 7;
    float cnt = fmaxf((float)g_bcnt[g], 1.0f);
    float s = 0.f;
#pragma unroll 8
    for (int k = 0; k < DDD; k++)
        s += g_pool[g * DDD + k] * __ldg(lw + k * CCC + c);
    out[tid] = s / cnt + __ldg(lb + c);
}

// ================= launch =================
extern "C" void kernel_launch(void* const* d_in, const int* in_sizes, int n_in,
                              void* d_out, int out_size) {
    const float* x     = (const float*)d_in[0];
    const float* W     = (const float*)d_in[1];
    const float* b     = (const float*)d_in[2];
    const float* lw    = (const float*)d_in[3];
    const float* lb    = (const float*)d_in[4];
    const int*   ei    = (const int*)d_in[5];
    const int*   batch = (const int*)d_in[6];
    float*       out   = (float*)d_out;

    cudaFuncSetAttribute(k_mma, cudaFuncAttributeMaxDynamicSharedMemorySize, MMA_SMEM);

    // fork: fp16 conversions run concurrently with the CSR build
    cudaStream_t s2;
    cudaEvent_t eFork, eJoin;
    cudaStreamCreateWithFlags(&s2, cudaStreamNonBlocking);
    cudaEventCreateWithFlags(&eFork, cudaEventDisableTiming);
    cudaEventCreateWithFlags(&eJoin, cudaEventDisableTiming);

    cudaEventRecord(eFork, 0);
    cudaStreamWaitEvent(s2, eFork, 0);
    k_cvt<<<(NN * 32 + 2 * 128 * 256 + 255) / 256, 256, 0, s2>>>(x, W);
    cudaEventRecord(eJoin, s2);

    // CSR build chain (main stream)
    k_zero<<<(2 * NN + 255) / 256, 256>>>();
    k_hist<<<(2 * EE + 255) / 256, 256>>>(ei);
    k_scanA<<<49, 256>>>();
    k_scanC<<<49, 256>>>();
    k_fill<<<(2 * EE + NN + 255) / 256, 256>>>(ei, batch);

    cudaStreamWaitEvent(0, eJoin, 0);

    int mma_blocks = (NN + 127) / 128;
    int gat_blocks = (NN * 32 + 255) / 256;

    // layer 0
    k_gather<<<gat_blocks, 256>>>();
    k_mma<<<mma_blocks, 256, MMA_SMEM>>>(b, batch, 0);

    // layer 1
    k_gather<<<gat_blocks, 256>>>();
    k_mma<<<mma_blocks, 256, MMA_SMEM>>>(b + 2 * DDD, batch, 1);

    // classify
    k_final<<<1, 512>>>(lw, lb, out);

    cudaEventDestroy(eFork);
    cudaEventDestroy(eJoin);
    cudaStreamDestroy(s2);
}

// round 16
// speedup vs baseline: 1.1454x; 1.0404x over previous
#include <cuda_runtime.h>
#include <cuda_fp16.h>
#include <cstdint>

#define NN 50000
#define EE 800000
#define DDD 128
#define GGG 64
#define CCC 8
#define M2 (2 * NN)          // scan domain: r0 nodes then r1 nodes
#define SCAN_BLOCKS 98       // 98 * 1024 >= 100000

// ---------------- scratch ----------------
__device__ __half    g_h16[NN * DDD];        // fp16 feature table (layer input)
__device__ __half    g_a16[NN * 256];        // aggregated A [node][256] fp16
__device__ __half    g_w16[2 * 128 * 256];   // Wt fp16 [layer][n][k]
__device__ int       g_ecnt[M2];             // per-relation in-degree
__device__ float     g_isd[M2];
__device__ int       g_off[M2];              // CSR offsets over combined (r,node) domain
__device__ int       g_cur[M2];              // fill cursors
__device__ int       g_btot[128];
__device__ unsigned  g_ebuf[2 * EE];         // src:16 | fp16(norm):16  (no relation bit needed)
__device__ int       g_bcnt[GGG];
__device__ float     g_pool[GGG * DDD];

// ================= helpers =================
__device__ __forceinline__ unsigned smem_u32(const void* p) {
    unsigned a;
    asm("{ .reg .u64 t; cvta.to.shared.u64 t, %1; cvt.u32.u64 %0, t; }" : "=r"(a) : "l"(p));
    return a;
}
__device__ __forceinline__ void cp16(unsigned dst, const void* gsrc, unsigned srcsize) {
    asm volatile("cp.async.cg.shared.global [%0], [%1], 16, %2;"
                 :: "r"(dst), "l"(__cvta_generic_to_global((void*)gsrc)), "r"(srcsize) : "memory");
}
__device__ __forceinline__ void cp_commit() { asm volatile("cp.async.commit_group;" ::: "memory"); }
template <int N> __device__ __forceinline__ void cp_wait() {
    asm volatile("cp.async.wait_group %0;" :: "n"(N) : "memory");
}
__device__ __forceinline__ void ldm_x4(unsigned& r0, unsigned& r1, unsigned& r2, unsigned& r3,
                                       unsigned addr) {
    asm volatile("ldmatrix.sync.aligned.m8n8.x4.shared.b16 {%0,%1,%2,%3}, [%4];"
                 : "=r"(r0), "=r"(r1), "=r"(r2), "=r"(r3) : "r"(addr));
}
__device__ __forceinline__ void mma_f16(float* d, const unsigned* a, const unsigned* b) {
    asm volatile("mma.sync.aligned.m16n8k16.row.col.f32.f16.f16.f32 "
                 "{%0,%1,%2,%3},{%4,%5,%6,%7},{%8,%9},{%0,%1,%2,%3};"
                 : "+f"(d[0]), "+f"(d[1]), "+f"(d[2]), "+f"(d[3])
                 : "r"(a[0]), "r"(a[1]), "r"(a[2]), "r"(a[3]), "r"(b[0]), "r"(b[1]));
}
__device__ __forceinline__ unsigned long long pack2(float lo, float hi) {
    unsigned long long r;
    asm("mov.b64 %0, {%1,%2};" : "=l"(r) : "f"(lo), "f"(hi));
    return r;
}
__device__ __forceinline__ float2 unpack2(unsigned long long v) {
    float2 f;
    asm("mov.b64 {%0,%1}, %2;" : "=f"(f.x), "=f"(f.y) : "l"(v));
    return f;
}
__device__ __forceinline__ void fma2(unsigned long long& a, unsigned long long x,
                                     unsigned long long n) {
    asm("fma.rn.f32x2 %0, %1, %2, %0;" : "+l"(a) : "l"(x), "l"(n));
}

// ================= prep kernels =================
__global__ void k_zero() {
    int i = blockIdx.x * blockDim.x + threadIdx.x;
    if (i < M2) g_ecnt[i] = 0;
}

__global__ void k_hist(const int* __restrict__ ei) {
    int i = blockIdx.x * blockDim.x + threadIdx.x;
    if (i >= 2 * EE) return;
    int r = (i >= EE) ? 1 : 0;
    int e = i - r * EE;
    int dst = __ldg(ei + (size_t)r * 2 * EE + EE + e);
    atomicAdd(&g_ecnt[r * NN + dst], 1);
}

// scan over M2 elements + isd + pool/bcnt zeroing
__global__ __launch_bounds__(256) void k_scanA() {
    __shared__ int sm[256];
    int bx = blockIdx.x, t = threadIdx.x;
    int gi = bx * 256 + t;
    if (gi < GGG * DDD) g_pool[gi] = 0.f;
    if (gi < GGG) g_bcnt[gi] = 0;
    int base = bx * 1024 + t * 4;
    int c[4];
#pragma unroll
    for (int j = 0; j < 4; j++) {
        int n = base + j;
        if (n < M2) {
            int cv = g_ecnt[n];
            g_isd[n] = rsqrtf((float)cv + 1.0f);
            c[j] = cv;
        } else c[j] = 0;
    }
    int s = c[0] + c[1] + c[2] + c[3];
    sm[t] = s;
    __syncthreads();
#pragma unroll
    for (int o = 1; o < 256; o <<= 1) {
        int v = (t >= o) ? sm[t - o] : 0;
        __syncthreads();
        sm[t] += v;
        __syncthreads();
    }
    int p = sm[t] - s;
#pragma unroll
    for (int j = 0; j < 4; j++) {
        int n = base + j;
        if (n < M2) g_off[n] = p;
        p += c[j];
    }
    if (t == 255) g_btot[bx] = sm[255];
}

// scanC with built-in block-offset reduction (SCAN_BLOCKS <= 128 < 256)
__global__ __launch_bounds__(256) void k_scanC() {
    __shared__ int wsum[8];
    __shared__ int boff_s;
    int bx = blockIdx.x, t = threadIdx.x;
    int v = (t < bx) ? g_btot[t] : 0;
#pragma unroll
    for (int o = 16; o; o >>= 1) v += __shfl_down_sync(~0u, v, o);
    if ((t & 31) == 0) wsum[t >> 5] = v;
    __syncthreads();
    if (t == 0) {
        int s = 0;
#pragma unroll
        for (int w = 0; w < 8; w++) s += wsum[w];
        boff_s = s;
    }
    __syncthreads();
    int boff = boff_s;
    int base = bx * 1024 + t * 4;
#pragma unroll
    for (int j = 0; j < 4; j++) {
        int n = base + j;
        if (n < M2) {
            int o = g_off[n] + boff;
            g_off[n] = o;
            g_cur[n] = o;
        }
    }
}

// edge fill (forward-only, one cursor) + batch histogram
__global__ void k_fill(const int* __restrict__ ei, const int* __restrict__ batch) {
    int i = blockIdx.x * blockDim.x + threadIdx.x;
    if (i < 2 * EE) {
        int r = (i >= EE) ? 1 : 0;
        int e = i - r * EE;
        int s = __ldg(ei + (size_t)r * 2 * EE + e);
        int d = __ldg(ei + (size_t)r * 2 * EE + EE + e);
        float nrm = g_isd[r * NN + s];
        unsigned hb = (unsigned)__half_as_ushort(__float2half(nrm));
        unsigned ent = (unsigned)s | (hb << 16);
        int pos = atomicAdd(&g_cur[r * NN + d], 1);
        g_ebuf[pos] = ent;
    } else if (i < 2 * EE + NN) {
        atomicAdd(&g_bcnt[__ldg(batch + i - 2 * EE)], 1);
    }
}

// fp16 conversions: features + transposed weights (runs on forked stream)
__global__ void k_cvt(const float* __restrict__ x, const float* __restrict__ W) {
    int i = blockIdx.x * blockDim.x + threadIdx.x;
    if (i < NN * 32) {
        float4 v = ((const float4*)x)[i];
        __half2 a = __floats2half2_rn(v.x, v.y);
        __half2 b = __floats2half2_rn(v.z, v.w);
        ((uint2*)g_h16)[i] = make_uint2(*(unsigned*)&a, *(unsigned*)&b);
    } else if (i < NN * 32 + 2 * 128 * 256) {
        int j = i - NN * 32;
        int l = j >> 15, n = (j >> 8) & 127, k = j & 255;
        int r = k >> 7, kd = k & 127;
        g_w16[j] = __float2half(__ldg(W + (((size_t)(l * 2 + r) * 128 + kd) * 128 + n)));
    }
}

// ================= gather: warp per node, split half-warps, relation-partitioned =================
__global__ __launch_bounds__(256) void k_gather() {
    int t = blockIdx.x * blockDim.x + threadIdx.x;
    int d    = t >> 5;                 // warp per node
    if (d >= NN) return;
    int lane = t & 31;
    int sub  = lane >> 4;              // 0: even entries, 1: odd entries
    int l16  = lane & 15;              // covers cols l16*8 .. l16*8+7

    unsigned long long a0[4], a1[4];
    unsigned long long z = pack2(0.f, 0.f);
#pragma unroll
    for (int q = 0; q < 4; q++) { a0[q] = z; a1[q] = z; }

    const uint4* h = (const uint4*)g_h16;

    // relation-0 region: [off[d], off[d+1])  (off[NN] = EE is the region end for d = NN-1)
    int r0s = g_off[d];
    int r0e = g_off[d + 1];
    // relation-1 region: [off[NN+d], off[NN+d+1]) with final end = 2*EE
    int r1s = g_off[NN + d];
    int r1e = (d < NN - 1) ? g_off[NN + d + 1] : 2 * EE;

#define PROC(v, ent, acc)                                                     \
    {                                                                         \
        const __half2* hp = (const __half2*)&(v);                             \
        float2 f0 = __half22float2(hp[0]);                                    \
        float2 f1 = __half22float2(hp[1]);                                    \
        float2 f2 = __half22float2(hp[2]);                                    \
        float2 f3 = __half22float2(hp[3]);                                    \
        float nrm = __half2float(__ushort_as_half(                            \
                        (unsigned short)((ent) >> 16)));                      \
        unsigned long long nn = pack2(nrm, nrm);                              \
        fma2((acc)[0], pack2(f0.x, f0.y), nn);                                \
        fma2((acc)[1], pack2(f1.x, f1.y), nn);                                \
        fma2((acc)[2], pack2(f2.x, f2.y), nn);                                \
        fma2((acc)[3], pack2(f3.x, f3.y), nn);                                \
    }

    int e = r0s + sub;
    for (; e + 2 < r0e; e += 4) {
        unsigned ea = g_ebuf[e];
        unsigned eb = g_ebuf[e + 2];
        uint4 va = h[(size_t)(ea & 0xFFFF) * 16 + l16];
        uint4 vb = h[(size_t)(eb & 0xFFFF) * 16 + l16];
        PROC(va, ea, a0);
        PROC(vb, eb, a0);
    }
    if (e < r0e) {
        unsigned ea = g_ebuf[e];
        uint4 va = h[(size_t)(ea & 0xFFFF) * 16 + l16];
        PROC(va, ea, a0);
    }

    e = r1s + sub;
    for (; e + 2 < r1e; e += 4) {
        unsigned ea = g_ebuf[e];
        unsigned eb = g_ebuf[e + 2];
        uint4 va = h[(size_t)(ea & 0xFFFF) * 16 + l16];
        uint4 vb = h[(size_t)(eb & 0xFFFF) * 16 + l16];
        PROC(va, ea, a1);
        PROC(vb, eb, a1);
    }
    if (e < r1e) {
        unsigned ea = g_ebuf[e];
        uint4 va = h[(size_t)(ea & 0xFFFF) * 16 + l16];
        PROC(va, ea, a1);
    }
#undef PROC

    // merge the two half-warp partial sums (lane i <-> lane i+16, same l16)
#pragma unroll
    for (int q = 0; q < 4; q++) {
        unsigned long long o0 = __shfl_xor_sync(~0u, a0[q], 16);
        unsigned long long o1 = __shfl_xor_sync(~0u, a1[q], 16);
        float2 A0 = unpack2(a0[q]), B0 = unpack2(o0);
        float2 A1 = unpack2(a1[q]), B1 = unpack2(o1);
        a0[q] = pack2(A0.x + B0.x, A0.y + B0.y);
        a1[q] = pack2(A1.x + B1.x, A1.y + B1.y);
    }

    // self-loop + isd[dst] scaling; sub 0 writes relation-0 block, sub 1 relation-1
    uint4 sv = h[(size_t)d * 16 + l16];
    const __half2* sp = (const __half2*)&sv;
    float2 s0 = __half22float2(sp[0]);
    float2 s1 = __half22float2(sp[1]);
    float2 s2 = __half22float2(sp[2]);
    float2 s3 = __half22float2(sp[3]);
    float hs[8] = {s0.x, s0.y, s1.x, s1.y, s2.x, s2.y, s3.x, s3.y};
    float isd = g_isd[sub * NN + d];
    float isd2 = isd * isd;

    union { uint4 q; __half2 h2[4]; } o;
#pragma unroll
    for (int q = 0; q < 4; q++) {
        float2 A = unpack2(sub ? a1[q] : a0[q]);
        float vx = isd * A.x + isd2 * hs[2 * q];
        float vy = isd * A.y + isd2 * hs[2 * q + 1];
        o.h2[q] = __floats2half2_rn(vx, vy);
    }
    *(uint4*)(g_a16 + (size_t)d * 256 + sub * 128 + l16 * 8) = o.q;
}

// ================= mma.sync fp16 GEMM =================
// smem: buf0 @0 (16KB: A 8K + B 8K), buf1 @16384, bias @32768
#define MMA_SMEM (32768 + 512)

__device__ __forceinline__ void load_chunk(unsigned sbuf, int row0, int kc, int layer, int tid) {
    const __half* wt = g_w16 + (size_t)layer * 32768;
#pragma unroll
    for (int t = 0; t < 4; t++) {
        int cid = tid + t * 256;
        int reg = cid >> 9;             // 0 = A, 1 = B
        int idx = cid & 511;
        int row = idx >> 2;
        int ch  = idx & 3;
        unsigned dst = sbuf + reg * 8192 + row * 64 + ((ch ^ ((row >> 1) & 3)) << 4);
        if (reg == 0) {
            int grow = row0 + row;
            unsigned ok = (grow < NN) ? 16u : 0u;
            int gr = (grow < NN) ? grow : (NN - 1);
            cp16(dst, g_a16 + (size_t)gr * 256 + kc * 32 + ch * 8, ok);
        } else {
            cp16(dst, wt + (size_t)row * 256 + kc * 32 + ch * 8, 16u);
        }
    }
}

__global__ __launch_bounds__(256) void k_mma(const float* __restrict__ bias,
                                             const int* __restrict__ batch,
                                             int layer) {
    extern __shared__ char smem[];
    unsigned sb = smem_u32(smem);
    int tid  = threadIdx.x;
    int lane = tid & 31;
    int wid  = tid >> 5;
    int wm   = wid & 1;
    int wn   = wid >> 1;
    int row0 = blockIdx.x * 128;

    float* bias_s = (float*)(smem + 32768);
    if (tid < 128) bias_s[tid] = __ldg(bias + tid) + __ldg(bias + 128 + tid);

    float acc[4][4][4];
#pragma unroll
    for (int mt = 0; mt < 4; mt++)
#pragma unroll
        for (int nt = 0; nt < 4; nt++)
#pragma unroll
            for (int q = 0; q < 4; q++) acc[mt][nt][q] = 0.f;

    load_chunk(sb, row0, 0, layer, tid);
    cp_commit();

    for (int c = 0; c < 8; c++) {
        if (c + 1 < 8) {
            load_chunk(sb + ((c + 1) & 1) * 16384, row0, c + 1, layer, tid);
            cp_commit();
            cp_wait<1>();
        } else {
            cp_wait<0>();
        }
        __syncthreads();

        unsigned sbuf = sb + (c & 1) * 16384;
#pragma unroll
        for (int s = 0; s < 2; s++) {
            unsigned ah[4][4], bh[4][2];
#pragma unroll
            for (int mt = 0; mt < 4; mt++) {
                int rl = wm * 64 + mt * 16 + ((lane >> 3) & 1) * 8 + (lane & 7);
                int ch = 2 * s + (lane >> 4);
                unsigned ad = sbuf + rl * 64 + ((ch ^ ((rl >> 1) & 3)) << 4);
                ldm_x4(ah[mt][0], ah[mt][1], ah[mt][2], ah[mt][3], ad);
            }
#pragma unroll
            for (int p = 0; p < 2; p++) {
                int rl = wn * 32 + p * 16 + ((lane >> 4) & 1) * 8 + (lane & 7);
                int ch = 2 * s + ((lane >> 3) & 1);
                unsigned bd = sbuf + 8192 + rl * 64 + ((ch ^ ((rl >> 1) & 3)) << 4);
                unsigned r0, r1, r2, r3;
                ldm_x4(r0, r1, r2, r3, bd);
                bh[2 * p][0] = r0;     bh[2 * p][1] = r1;
                bh[2 * p + 1][0] = r2; bh[2 * p + 1][1] = r3;
            }
#pragma unroll
            for (int mt = 0; mt < 4; mt++)
#pragma unroll
                for (int nt = 0; nt < 4; nt++)
                    mma_f16(acc[mt][nt], ah[mt], bh[nt]);
        }
        __syncthreads();
    }

    // ---- epilogue ----
#pragma unroll
    for (int mt = 0; mt < 4; mt++) {
        int gm0 = row0 + wm * 64 + mt * 16 + (lane >> 2);
#pragma unroll
        for (int half = 0; half < 2; half++) {
            int gm = gm0 + half * 8;
            if (gm >= NN) continue;
            if (layer == 0) {
#pragma unroll
                for (int nt = 0; nt < 4; nt++) {
                    int cn = wn * 32 + nt * 8 + (lane & 3) * 2;
                    float v0 = fmaxf(acc[mt][nt][half * 2 + 0] + bias_s[cn], 0.f);
                    float v1 = fmaxf(acc[mt][nt][half * 2 + 1] + bias_s[cn + 1], 0.f);
                    *(__half2*)(g_h16 + (size_t)gm * 128 + cn) = __floats2half2_rn(v0, v1);
                }
            } else {
                int g = __ldg(batch + gm);
#pragma unroll
                for (int nt = 0; nt < 4; nt++) {
                    int cn = wn * 32 + nt * 8 + (lane & 3) * 2;
                    float v0 = acc[mt][nt][half * 2 + 0] + bias_s[cn];
                    float v1 = acc[mt][nt][half * 2 + 1] + bias_s[cn + 1];
                    float* p = g_pool + (size_t)g * 128 + cn;
                    asm volatile("red.global.add.v2.f32 [%0], {%1,%2};"
                                 :: "l"(p), "f"(v0), "f"(v1) : "memory");
                }
            }
        }
    }
}

// ================= final linear =================
__global__ void k_final(const float* __restrict__ lw, const float* __restrict__ lb,
                        float* __restrict__ out) {
    int tid = threadIdx.x;
    if (tid >= GGG * CCC) return;
    int g = tid >> 3, c = tid & 7;
    float cnt = fmaxf((float)g_bcnt[g], 1.0f);
    float s = 0.f;
#pragma unroll 8
    for (int k = 0; k < DDD; k++)
        s += g_pool[g * DDD + k] * __ldg(lw + k * CCC + c);
    out[tid] = s / cnt + __ldg(lb + c);
}

// ================= launch =================
extern "C" void kernel_launch(void* const* d_in, const int* in_sizes, int n_in,
                              void* d_out, int out_size) {
    const float* x     = (const float*)d_in[0];
    const float* W     = (const float*)d_in[1];
    const float* b     = (const float*)d_in[2];
    const float* lw    = (const float*)d_in[3];
    const float* lb    = (const float*)d_in[4];
    const int*   ei    = (const int*)d_in[5];
    const int*   batch = (const int*)d_in[6];
    float*       out   = (float*)d_out;

    cudaFuncSetAttribute(k_mma, cudaFuncAttributeMaxDynamicSharedMemorySize, MMA_SMEM);

    // fork: fp16 conversions run concurrently with the CSR build
    cudaStream_t s2;
    cudaEvent_t eFork, eJoin;
    cudaStreamCreateWithFlags(&s2, cudaStreamNonBlocking);
    cudaEventCreateWithFlags(&eFork, cudaEventDisableTiming);
    cudaEventCreateWithFlags(&eJoin, cudaEventDisableTiming);

    cudaEventRecord(eFork, 0);
    cudaStreamWaitEvent(s2, eFork, 0);
    k_cvt<<<(NN * 32 + 2 * 128 * 256 + 255) / 256, 256, 0, s2>>>(x, W);
    cudaEventRecord(eJoin, s2);

    // CSR build chain (main stream)
    k_zero<<<(M2 + 255) / 256, 256>>>();
    k_hist<<<(2 * EE + 255) / 256, 256>>>(ei);
    k_scanA<<<SCAN_BLOCKS, 256>>>();
    k_scanC<<<SCAN_BLOCKS, 256>>>();
    k_fill<<<(2 * EE + NN + 255) / 256, 256>>>(ei, batch);

    cudaStreamWaitEvent(0, eJoin, 0);

    int mma_blocks = (NN + 127) / 128;
    int gat_blocks = (NN * 32 + 255) / 256;

    // layer 0
    k_gather<<<gat_blocks, 256>>>();
    k_mma<<<mma_blocks, 256, MMA_SMEM>>>(b, batch, 0);

    // layer 1
    k_gather<<<gat_blocks, 256>>>();
    k_mma<<<mma_blocks, 256, MMA_SMEM>>>(b + 2 * DDD, batch, 1);

    // classify
    k_final<<<1, 512>>>(lw, lb, out);

    cudaEventDestroy(eFork);
    cudaEventDestroy(eJoin);
    cudaStreamDestroy(s2);
}